// round 13
// baseline (speedup 1.0000x reference)
#include <cuda_runtime.h>

#define NFEAT 17
#define NEV 16
#define PPE 65536
#define NPTS (NEV * PPE)
#define T_B 0.2f
#define R2C 0.49f

#define BPE 8                 // blocks per event
#define SLICE (PPE / BPE)     // 8192 points per block
#define PPT 8                 // candidate slots per thread (sorted desc in smem)
#define MAXI 64
#define NSLOT (NEV * MAXI * BPE)   // mailbox slots, 4 u64 words each

// ---- device scratch (no allocation allowed) ----
__device__ float4             g_pts[NPTS];
__device__ unsigned long long g_pub[NSLOT * 4];   // [key, xy, z, pad]
__device__ int                g_ccnt[NEV];
__device__ int                g_done;

// ---------------------------------------------------------------------------
// K1: zero output (streaming stores) + pack pts + zero mailbox flags.
// ---------------------------------------------------------------------------
__global__ void zero_pack_kernel(const float* __restrict__ x,
                                 float* __restrict__ out, long long n) {
    const long long gid    = (long long)blockIdx.x * blockDim.x + threadIdx.x;
    const long long stride = (long long)gridDim.x * blockDim.x;

    const long long n4 = n >> 2;
    const float4 z = make_float4(0.f, 0.f, 0.f, 0.f);
    for (long long j = gid; j < n4; j += stride)
        __stcs(reinterpret_cast<float4*>(out) + j, z);
    if (gid < (n & 3)) __stcs(out + (n4 << 2) + gid, 0.f);

    if (gid < NSLOT) g_pub[gid * 4] = 0ULL;   // flag word only
    if (gid == 0)    g_done = 0;

    if (gid < NPTS) {
        const float* r = x + gid * NFEAT;
        float4 p;
        p.x = __ldcs(r + 14);
        p.y = __ldcs(r + 15);
        p.z = __ldcs(r + 16);
        p.w = __ldcs(r + 9);
        g_pts[gid] = p;
    }
}

// ---------------------------------------------------------------------------
// K2: condensation + scatter + splits. 8 blocks/event, 1024 thr, single wave.
//   Per-thread candidates sorted desc by key in smem columns; register head
//   with invariant "checked vs all refs so far" -> O(1) work per iteration.
//   Key = (beta_bits<<32)|(~row): max == (max beta, min idx) == jnp.argmax.
// ---------------------------------------------------------------------------
__global__ void __launch_bounds__(1024, 1)
condense_kernel(const float* __restrict__ x, float* __restrict__ out,
                long long splits_off, int do_splits) {
    extern __shared__ char dyn[];
    unsigned long long* skey = (unsigned long long*)dyn;       // [PPT*1024]
    float4*             sco  = (float4*)(skey + PPT * 1024);   // [PPT*1024]

    __shared__ unsigned long long swk[32];
    __shared__ unsigned long long s_bk;      // block max key
    __shared__ unsigned long long s_key;     // global winner key
    __shared__ float s_cx, s_cy, s_cz;
    __shared__ float rx[MAXI], ry[MAXI], rz[MAXI];
    __shared__ int s_rows[MAXI];

    const int blk  = blockIdx.x;
    const int e    = blk / BPE;
    const int sub  = blk - e * BPE;
    const int t    = threadIdx.x;
    const int lane = t & 31;
    const int warp = t >> 5;
    const int base = e * PPE + sub * SLICE;

    // ---- load slice into smem columns ----
    #pragma unroll
    for (int k = 0; k < PPT; ++k) {
        const int i = base + t + (k << 10);
        const float4 p = g_pts[i];
        skey[(k << 10) + t] = (p.w >= T_B)
            ? (((unsigned long long)__float_as_uint(p.w) << 32) |
               (unsigned)(~(unsigned)i))
            : 0ULL;
        sco[(k << 10) + t] = p;
    }
    // ---- selection-sort own column desc by key (thread-private, no sync) ----
    for (int a = 0; a < PPT - 1; ++a) {
        int best = a;
        unsigned long long kb = skey[(a << 10) + t];
        for (int b = a + 1; b < PPT; ++b) {
            const unsigned long long k2 = skey[(b << 10) + t];
            if (k2 > kb) { kb = k2; best = b; }
        }
        if (best != a) {
            const unsigned long long ka = skey[(a << 10) + t];
            skey[(a << 10) + t] = kb;
            skey[(best << 10) + t] = ka;
            const float4 ca = sco[(a << 10) + t];
            sco[(a << 10) + t] = sco[(best << 10) + t];
            sco[(best << 10) + t] = ca;
        }
    }

    int head = 0;
    unsigned long long hkey = skey[t];
    float4 hc = sco[t];
    if (hkey == 0ULL) head = PPT;

    int count = 0;

    for (int it = 0; it < MAXI; ++it) {
        // ---- block argmax of heads (key only) ----
        unsigned long long bk = (head < PPT) ? hkey : 0ULL;
        #pragma unroll
        for (int off = 16; off > 0; off >>= 1) {
            const unsigned long long o = __shfl_down_sync(0xFFFFFFFFu, bk, off);
            if (o > bk) bk = o;
        }
        if (lane == 0) swk[warp] = bk;
        __syncthreads();                                   // bar1
        if (warp == 0) {
            unsigned long long v = swk[lane];
            #pragma unroll
            for (int off = 16; off > 0; off >>= 1) {
                const unsigned long long o = __shfl_down_sync(0xFFFFFFFFu, v, off);
                if (o > v) v = o;
            }
            if (lane == 0) s_bk = v;
        }
        __syncthreads();                                   // bar2

        // ---- publish: unique winning thread carries its coords ----
        const unsigned long long blockkey = s_bk;
        volatile unsigned long long* slot0 =
            g_pub + ((e * MAXI + it) * BPE) * 4;
        if (blockkey != 0ULL) {
            if (head < PPT && hkey == blockkey) {
                volatile unsigned long long* own = slot0 + sub * 4;
                own[1] = ((unsigned long long)__float_as_uint(hc.x) << 32) |
                         __float_as_uint(hc.y);
                own[2] = (unsigned long long)__float_as_uint(hc.z);
                __threadfence();
                own[0] = blockkey;
            }
        } else if (t == 0) {
            slot0[sub * 4] = 1ULL;                         // empty sentinel
        }

        // ---- warp0: poll 8 slots + reduce (key, coords) ----
        if (warp == 0) {
            unsigned long long pk = 0ULL, pxy = 0ULL, pzz = 0ULL;
            if (lane < 8) {
                volatile unsigned long long* sl = slot0 + lane * 4;
                while ((pk = sl[0]) == 0ULL) { }
                pxy = sl[1];
                pzz = sl[2];
            }
            #pragma unroll
            for (int off = 4; off > 0; off >>= 1) {
                const unsigned long long ok  = __shfl_down_sync(0xFFFFFFFFu, pk,  off);
                const unsigned long long oxy = __shfl_down_sync(0xFFFFFFFFu, pxy, off);
                const unsigned long long ozz = __shfl_down_sync(0xFFFFFFFFu, pzz, off);
                if (ok > pk) { pk = ok; pxy = oxy; pzz = ozz; }
            }
            if (lane == 0) {
                s_key = pk;
                s_cx = __uint_as_float((unsigned)(pxy >> 32));
                s_cy = __uint_as_float((unsigned)pxy);
                s_cz = __uint_as_float((unsigned)pzz);
            }
        }
        __syncthreads();                                   // bar3

        const unsigned long long wk = s_key;
        if (__uint_as_float((unsigned)(wk >> 32)) < T_B) break;

        const float cx = s_cx, cy = s_cy, cz = s_cz;
        if (t == 0) {
            s_rows[count] = (int)(~(unsigned)(wk & 0xFFFFFFFFull));
            rx[count] = cx; ry[count] = cy; rz[count] = cz;
        }

        // ---- O(1) update: check head vs new ref; advance on death ----
        if (head < PPT) {
            const float dx = hc.x - cx;
            const float dy = hc.y - cy;
            const float dz = hc.z - cz;
            if (dx * dx + dy * dy + dz * dz <= R2C) {
                ++head;
                while (head < PPT) {
                    const unsigned long long k2 = skey[(head << 10) + t];
                    if (k2 == 0ULL) { head = PPT; break; }
                    const float4 c = sco[(head << 10) + t];
                    bool dead;
                    {   // vs newest ref (registers)
                        const float ax = c.x - cx, ay = c.y - cy, az = c.z - cz;
                        dead = (ax * ax + ay * ay + az * az <= R2C);
                    }
                    if (!dead) {
                        for (int r = 0; r < count; ++r) {  // vs older refs
                            const float ax = c.x - rx[r];
                            const float ay = c.y - ry[r];
                            const float az = c.z - rz[r];
                            if (ax * ax + ay * ay + az * az <= R2C) { dead = true; break; }
                        }
                    }
                    if (!dead) { hkey = k2; hc = c; break; }
                    ++head;
                }
            }
        }
        ++count;
        __syncthreads();   // bar4: t0's rx[count-1] visible before next advance
    }

    // ---- tail: scatter this event's rows (sub 0) + splits (last event) ----
    __syncthreads();
    if (sub == 0) {
        for (int c = warp; c < count; c += 32) {
            const long long row = (long long)s_rows[c];
            if (lane < NFEAT)
                out[row * NFEAT + lane] = x[row * NFEAT + lane];
        }
        if (t == 0) {
            *(volatile int*)&g_ccnt[e] = count;
            __threadfence();
            if (do_splits) {
                const int old = atomicAdd(&g_done, 1);
                if (old == NEV - 1) {
                    __threadfence();
                    int acc = 0;
                    out[splits_off] = 0.0f;
                    #pragma unroll
                    for (int ev = 0; ev < NEV; ++ev) {
                        acc += *(volatile int*)&g_ccnt[ev];
                        out[splits_off + 1 + ev] = (float)acc;
                    }
                }
            }
        }
    }
}

// ---------------------------------------------------------------------------
extern "C" void kernel_launch(void* const* d_in, const int* in_sizes, int n_in,
                              void* d_out, int out_size) {
    const float* x   = (const float*)d_in[0];
    float*       out = (float*)d_out;
    const long long n = (long long)out_size;

    // dyn smem: PPT*1024*(8+16) = 196608 B (< 227 KB cap, 1 block/SM)
    static const size_t dyn_smem = (size_t)PPT * 1024 * 24;
    cudaFuncSetAttribute(condense_kernel,
                         cudaFuncAttributeMaxDynamicSharedMemorySize,
                         (int)dyn_smem);

    // 1) fused zero(streaming) + pack + mailbox init
    zero_pack_kernel<<<NPTS / 256, 256>>>(x, out, n);

    // 2) condense + scatter + splits (128 blocks: single wave, poll-safe)
    const long long dout_elems = (long long)NPTS * NFEAT;
    const int do_splits = (n == dout_elems + NEV + 1) ? 1 : 0;
    condense_kernel<<<NEV * BPE, 1024, dyn_smem>>>(x, out, dout_elems, do_splits);
}

// round 16
// speedup vs baseline: 1.3615x; 1.3615x over previous
#include <cuda_runtime.h>

#define NFEAT 17
#define NEV 16
#define PPE 65536
#define NPTS (NEV * PPE)
#define T_B 0.2f
#define R2C 0.49f

#define BPE 16                // blocks per event (one 4096-pt slice each)
#define SLICE (PPE / BPE)     // 4096
#define THREADS 512
#define PPT (SLICE / THREADS) // 8, register-resident
#define MAXI 64
#define NKEY (NEV * MAXI * BPE)

// ---- device scratch (no allocation allowed) ----
__device__ float4             g_pts[NPTS];   // (x,y,z,beta)
__device__ unsigned long long g_key[NKEY];   // mailbox: one u64 key per block/iter
__device__ int                g_ccnt[NEV];
__device__ int                g_done;

// ---------------------------------------------------------------------------
// K1: zero output (streaming stores) + pack pts + zero mailbox/done counter.
// ---------------------------------------------------------------------------
__global__ void zero_pack_kernel(const float* __restrict__ x,
                                 float* __restrict__ out, long long n) {
    const long long gid    = (long long)blockIdx.x * blockDim.x + threadIdx.x;
    const long long stride = (long long)gridDim.x * blockDim.x;

    const long long n4 = n >> 2;
    const float4 z = make_float4(0.f, 0.f, 0.f, 0.f);
    for (long long j = gid; j < n4; j += stride)
        __stcs(reinterpret_cast<float4*>(out) + j, z);   // evict-first
    if (gid < (n & 3)) __stcs(out + (n4 << 2) + gid, 0.f);

    if (gid < NKEY) g_key[gid] = 0ULL;
    if (gid == 0)   g_done = 0;

    if (gid < NPTS) {
        const float* r = x + gid * NFEAT;
        float4 p;
        p.x = __ldcs(r + 14);
        p.y = __ldcs(r + 15);
        p.z = __ldcs(r + 16);
        p.w = __ldcs(r + 9);
        g_pts[gid] = p;          // normal store: stays hot in L2
    }
}

// ---------------------------------------------------------------------------
// K2: condensation + scatter + splits. 16 blocks/event, 512 thr, 2 blocks/SM
//   (single wave of 256 <= 296 — spin-safe; co-resident blocks hide each
//   other's exchange latency). Candidates REGISTER-resident (p[8]).
//   Key = (beta_bits<<32)|(~row): max key == (max beta, min idx) == jnp.argmax.
//   Exchange: 8B volatile key store (atomic, key-as-flag, fresh slot/iter);
//   lanes 0..15 poll the 16 slots (one 128B L2 line) + speculatively load
//   their slot's candidate coords in parallel.
// ---------------------------------------------------------------------------
__global__ void __launch_bounds__(THREADS, 2)
condense_kernel(const float* __restrict__ x, float* __restrict__ out,
                long long splits_off, int do_splits) {
    __shared__ unsigned long long swk[16];
    __shared__ unsigned long long s_key;
    __shared__ float s_cx, s_cy, s_cz;
    __shared__ int s_rows[MAXI];

    const int blk  = blockIdx.x;
    const int e    = blk / BPE;
    const int sub  = blk - e * BPE;
    const int t    = threadIdx.x;
    const int lane = t & 31;
    const int warp = t >> 5;                  // 0..15
    const int base = e * PPE + sub * SLICE;

    // ---- load slice into registers + initial per-thread (beta, idx) ----
    float4 p[PPT];
    float bw = -1.0f;
    int   bi = 0;
    #pragma unroll
    for (int k = 0; k < PPT; ++k) {
        const int i = base + t + (k << 9);    // stride THREADS=512
        p[k] = g_pts[i];
        if (p[k].w >= T_B) {
            if (p[k].w > bw) { bw = p[k].w; bi = i; }   // ascending i: '>' keeps first
        } else {
            p[k].w = -1.0f;
        }
    }

    int count = 0;

    for (int it = 0; it < MAXI; ++it) {
        // ---- warp argmax of (beta, idx), min-idx tie-break ----
        #pragma unroll
        for (int off = 16; off > 0; off >>= 1) {
            const float ow = __shfl_down_sync(0xFFFFFFFFu, bw, off);
            const int   oi = __shfl_down_sync(0xFFFFFFFFu, bi, off);
            if (ow > bw || (ow == bw && oi < bi)) { bw = ow; bi = oi; }
        }
        if (lane == 0) {
            swk[warp] = (bw >= T_B)
                ? (((unsigned long long)__float_as_uint(bw) << 32) |
                   (unsigned)(~(unsigned)bi))
                : 0ULL;
        }
        __syncthreads();
        if (warp == 0) {
            unsigned long long v = (lane < 16) ? swk[lane] : 0ULL;
            #pragma unroll
            for (int off = 8; off > 0; off >>= 1) {
                const unsigned long long o = __shfl_down_sync(0xFFFFFFFFu, v, off);
                if (o > v) v = o;
            }
            // lane 0 now holds the block max over lanes 0..15
            if (lane == 0) {
                const unsigned long long pubk = v ? v : 1ULL;   // sentinel: empty
                unsigned long long* own = g_key + (e * MAXI + it) * BPE + sub;
                asm volatile("st.volatile.global.b64 [%0], %1;"
                             :: "l"(own), "l"(pubk) : "memory");
            }
            __syncwarp();
            // ---- poll the 16 slots + speculative coord load per lane ----
            unsigned long long pk = 0ULL;
            float px = 0.f, py = 0.f, pz = 0.f;
            if (lane < 16) {
                const unsigned long long* sl = g_key + (e * MAXI + it) * BPE + lane;
                do {
                    asm volatile("ld.volatile.global.b64 %0, [%1];"
                                 : "=l"(pk) : "l"(sl));
                } while (pk == 0ULL);
                if (pk != 1ULL) {
                    const int row = (int)(~(unsigned)(pk & 0xFFFFFFFFull));
                    const float4 rp = g_pts[row];   // 16 parallel L2 loads
                    px = rp.x; py = rp.y; pz = rp.z;
                }
            }
            #pragma unroll
            for (int off = 8; off > 0; off >>= 1) {
                const unsigned long long ok = __shfl_down_sync(0xFFFFFFFFu, pk, off);
                const float ox = __shfl_down_sync(0xFFFFFFFFu, px, off);
                const float oy = __shfl_down_sync(0xFFFFFFFFu, py, off);
                const float oz = __shfl_down_sync(0xFFFFFFFFu, pz, off);
                if (ok > pk) { pk = ok; px = ox; py = oy; pz = oz; }
            }
            if (lane == 0) {
                s_key = pk;
                s_cx = px; s_cy = py; s_cz = pz;
            }
        }
        __syncthreads();

        const unsigned long long wk = s_key;
        const float wb = __uint_as_float((unsigned)(wk >> 32));
        if (wb < T_B) break;

        if (t == 0) s_rows[count] = (int)(~(unsigned)(wk & 0xFFFFFFFFull));
        ++count;

        const float cx = s_cx, cy = s_cy, cz = s_cz;

        // ---- register pass: suppress + next per-thread (beta, idx) ----
        bw = -1.0f; bi = 0;
        #pragma unroll
        for (int k = 0; k < PPT; ++k) {
            const float w = p[k].w;
            if (w >= 0.0f) {
                const float dx = p[k].x - cx;
                const float dy = p[k].y - cy;
                const float dz = p[k].z - cz;
                if (dx * dx + dy * dy + dz * dz <= R2C) {
                    p[k].w = -1.0f;
                } else if (w > bw) {
                    bw = w;
                    bi = base + t + (k << 9);
                }
            }
        }
    }

    // ---- tail: scatter this event's rows (sub 0) + splits (last event) ----
    __syncthreads();
    if (sub == 0) {
        const int nw = THREADS >> 5;
        for (int c = warp; c < count; c += nw) {
            const long long row = (long long)s_rows[c];
            if (lane < NFEAT)
                out[row * NFEAT + lane] = x[row * NFEAT + lane];
        }
        if (t == 0) {
            *(volatile int*)&g_ccnt[e] = count;
            __threadfence();
            if (do_splits) {
                const int old = atomicAdd(&g_done, 1);
                if (old == NEV - 1) {
                    __threadfence();
                    int acc = 0;
                    out[splits_off] = 0.0f;
                    #pragma unroll
                    for (int ev = 0; ev < NEV; ++ev) {
                        acc += *(volatile int*)&g_ccnt[ev];
                        out[splits_off + 1 + ev] = (float)acc;
                    }
                }
            }
        }
    }
}

// ---------------------------------------------------------------------------
extern "C" void kernel_launch(void* const* d_in, const int* in_sizes, int n_in,
                              void* d_out, int out_size) {
    const float* x   = (const float*)d_in[0];
    float*       out = (float*)d_out;
    const long long n = (long long)out_size;

    // 1) fused zero(streaming) + pack + mailbox init
    zero_pack_kernel<<<NPTS / 256, 256>>>(x, out, n);

    // 2) condense + scatter + splits (256 blocks, 2/SM: single wave, poll-safe)
    const long long dout_elems = (long long)NPTS * NFEAT;
    const int do_splits = (n == dout_elems + NEV + 1) ? 1 : 0;
    condense_kernel<<<NEV * BPE, THREADS>>>(x, out, dout_elems, do_splits);
}

// round 17
// speedup vs baseline: 1.4054x; 1.0322x over previous
#include <cuda_runtime.h>

#define NFEAT 17
#define NEV 16
#define PPE 65536
#define NPTS (NEV * PPE)
#define T_B 0.2f
#define R2C 0.49f

#define BPE 8                  // blocks per event (8192-pt slice each)
#define SLICE (PPE / BPE)
#define PPT 8                  // register-resident points per thread
#define MAXI 64                // max exchange rounds
#define RCAP 8                 // max refs accepted per round
#define MAXREF 64              // total ref capacity (geometric bound ~30)
#define NKW (NEV * MAXI * BPE * 2)   // mailbox words: [key1|flag, key2] per slot
#define TBKEY 0x3E4CCCCD00000000ull  // key of beta=0.2, idx-part 0

// ---- device scratch (no allocation allowed) ----
__device__ float4             g_pts[NPTS];
__device__ unsigned long long g_key[NKW];
__device__ int                g_ccnt[NEV];
__device__ int                g_done;

// ---------------------------------------------------------------------------
// K1: zero output (streaming stores) + pack pts + zero mailbox words.
// ---------------------------------------------------------------------------
__global__ void zero_pack_kernel(const float* __restrict__ x,
                                 float* __restrict__ out, long long n) {
    const long long gid    = (long long)blockIdx.x * blockDim.x + threadIdx.x;
    const long long stride = (long long)gridDim.x * blockDim.x;

    const long long n4 = n >> 2;
    const float4 z = make_float4(0.f, 0.f, 0.f, 0.f);
    for (long long j = gid; j < n4; j += stride)
        __stcs(reinterpret_cast<float4*>(out) + j, z);
    if (gid < (n & 3)) __stcs(out + (n4 << 2) + gid, 0.f);

    if (gid < NKW) g_key[gid] = 0ULL;
    if (gid == 0)  g_done = 0;

    if (gid < NPTS) {
        const float* r = x + gid * NFEAT;
        float4 p;
        p.x = __ldcs(r + 14);
        p.y = __ldcs(r + 15);
        p.z = __ldcs(r + 16);
        p.w = __ldcs(r + 9);
        g_pts[gid] = p;
    }
}

// merge two key-sorted pairs (a1>=a2), (o1>=o2) -> top-2
__device__ __forceinline__ void pair_merge(unsigned long long& a1,
                                           unsigned long long& a2,
                                           unsigned long long o1,
                                           unsigned long long o2) {
    if (o1 > a1) { a2 = (a1 > o2) ? a1 : o2; a1 = o1; }
    else if (o1 > a2) { a2 = o1; }
}

// ---------------------------------------------------------------------------
// K2: batched greedy condensation + scatter + splits. 8 blocks/event,
//   1024 thr, single wave. Key=(beta_bits<<32)|(~row): max == jnp.argmax.
//   Each round: blocks publish top-2 alive keys; warp0 polls all 8 slots,
//   fetches coords, runs an exact certified mini-greedy over 16 entries
//   (accept while S >= F = max of all key2 floors), suppresses all accepted
//   refs in ONE register pass.
// ---------------------------------------------------------------------------
__global__ void __launch_bounds__(1024, 1)
condense_kernel(const float* __restrict__ x, float* __restrict__ out,
                long long splits_off, int do_splits) {
    __shared__ unsigned long long sw1[32], sw2[32];
    __shared__ int s_nref;
    __shared__ float s_rx[RCAP], s_ry[RCAP], s_rz[RCAP];
    __shared__ int s_rows[MAXREF];

    const int blk  = blockIdx.x;
    const int e    = blk / BPE;
    const int sub  = blk - e * BPE;
    const int t    = threadIdx.x;
    const int lane = t & 31;
    const int warp = t >> 5;
    const int base = e * PPE + sub * SLICE;

    // ---- load slice into registers + initial per-thread top-2 keys ----
    float4 p[PPT];
    unsigned long long k1 = 0ULL, k2 = 0ULL;
    #pragma unroll
    for (int k = 0; k < PPT; ++k) {
        const int i = base + t + (k << 10);
        p[k] = g_pts[i];
        if (p[k].w >= T_B) {
            const unsigned long long key =
                ((unsigned long long)__float_as_uint(p[k].w) << 32) |
                (unsigned)(~(unsigned)i);
            if (key > k1) { k2 = k1; k1 = key; }
            else if (key > k2) { k2 = key; }
        } else {
            p[k].w = -1.0f;
        }
    }

    int count = 0;

    for (int round = 0; round < MAXI; ++round) {
        // ---- warp reduce of top-2 pairs ----
        #pragma unroll
        for (int off = 16; off > 0; off >>= 1) {
            const unsigned long long o1 = __shfl_down_sync(0xFFFFFFFFu, k1, off);
            const unsigned long long o2 = __shfl_down_sync(0xFFFFFFFFu, k2, off);
            pair_merge(k1, k2, o1, o2);
        }
        if (lane == 0) { sw1[warp] = k1; sw2[warp] = k2; }
        __syncthreads();

        if (warp == 0) {
            // ---- block top-2 over 32 warp pairs ----
            unsigned long long a1 = sw1[lane], a2 = sw2[lane];
            #pragma unroll
            for (int off = 16; off > 0; off >>= 1) {
                const unsigned long long o1 = __shfl_down_sync(0xFFFFFFFFu, a1, off);
                const unsigned long long o2 = __shfl_down_sync(0xFFFFFFFFu, a2, off);
                pair_merge(a1, a2, o1, o2);
            }
            unsigned long long* slotbase = g_key + ((e * MAXI + round) * BPE) * 2;
            // ---- publish: key2, fence, key1-as-flag ----
            if (lane == 0) {
                volatile unsigned long long* own = slotbase + sub * 2;
                own[1] = a2;
                __threadfence();
                own[0] = a1 ? a1 : 1ULL;     // sentinel for empty block
            }
            __syncwarp();
            // ---- poll 8 slots; lanes 0..7 take key1, 8..15 take key2 ----
            unsigned long long ekey = 0ULL;
            float ex = 0.f, ey = 0.f, ez = 0.f;
            if (lane < 16) {
                const int b = lane & 7;
                volatile unsigned long long* sl = slotbase + b * 2;
                unsigned long long f;
                do { f = sl[0]; } while (f == 0ULL);
                if (lane < 8) {
                    ekey = (f == 1ULL) ? 0ULL : f;
                } else {
                    __threadfence();          // order data read after flag
                    ekey = sl[1];
                }
                if (ekey >= TBKEY) {
                    const int row = (int)(~(unsigned)(ekey & 0xFFFFFFFFull));
                    const float4 rp = g_pts[row];   // parallel L2 loads
                    ex = rp.x; ey = rp.y; ez = rp.z;
                } else {
                    ekey = 0ULL;
                }
            }
            // ---- floor F = max over key2 entries (lanes 8..15) ----
            unsigned long long fk = (lane >= 8 && lane < 16) ? ekey : 0ULL;
            #pragma unroll
            for (int off = 16; off > 0; off >>= 1) {
                const unsigned long long o = __shfl_xor_sync(0xFFFFFFFFu, fk, off);
                if (o > fk) fk = o;
            }
            // ---- certified mini-greedy over the 16 entries ----
            bool alive = (ekey != 0ULL);
            int nref = 0;
            while (true) {
                unsigned long long mk = alive ? ekey : 0ULL;
                float mx = ex, my = ey, mz = ez;
                #pragma unroll
                for (int off = 16; off > 0; off >>= 1) {
                    const unsigned long long o = __shfl_xor_sync(0xFFFFFFFFu, mk, off);
                    const float ox = __shfl_xor_sync(0xFFFFFFFFu, mx, off);
                    const float oy = __shfl_xor_sync(0xFFFFFFFFu, my, off);
                    const float oz = __shfl_xor_sync(0xFFFFFFFFu, mz, off);
                    if (o > mk) { mk = o; mx = ox; my = oy; mz = oz; }
                }
                if (mk < TBKEY) break;                      // no valid candidate
                if (nref > 0 && mk < fk) break;             // certification fails
                if (lane == 0) {
                    s_rx[nref] = mx; s_ry[nref] = my; s_rz[nref] = mz;
                    s_rows[count + nref] = (int)(~(unsigned)(mk & 0xFFFFFFFFull));
                }
                if (alive) {
                    const float dx = ex - mx;
                    const float dy = ey - my;
                    const float dz = ez - mz;
                    if (dx * dx + dy * dy + dz * dz <= R2C) alive = false;
                }
                ++nref;
                if (nref == RCAP) break;
                if (count + nref >= MAXREF) break;
            }
            if (lane == 0) s_nref = nref;
        }
        __syncthreads();

        const int nref = s_nref;
        if (nref == 0) break;
        count += nref;

        // ---- register pass: suppress vs all round refs, rebuild top-2 ----
        k1 = 0ULL; k2 = 0ULL;
        #pragma unroll
        for (int k = 0; k < PPT; ++k) {
            const float w = p[k].w;
            if (w < 0.0f) continue;
            bool dead = false;
            for (int r = 0; r < nref; ++r) {
                const float dx = p[k].x - s_rx[r];
                const float dy = p[k].y - s_ry[r];
                const float dz = p[k].z - s_rz[r];
                if (dx * dx + dy * dy + dz * dz <= R2C) { dead = true; break; }
            }
            if (dead) { p[k].w = -1.0f; continue; }
            const unsigned long long key =
                ((unsigned long long)__float_as_uint(w) << 32) |
                (unsigned)(~(unsigned)(base + t + (k << 10)));
            if (key > k1) { k2 = k1; k1 = key; }
            else if (key > k2) { k2 = key; }
        }
        if (count >= MAXREF) break;
    }

    // ---- tail: scatter this event's rows (sub 0) + splits (last event) ----
    __syncthreads();
    if (sub == 0) {
        for (int c = warp; c < count; c += 32) {
            const long long row = (long long)s_rows[c];
            if (lane < NFEAT)
                out[row * NFEAT + lane] = x[row * NFEAT + lane];
        }
        if (t == 0) {
            *(volatile int*)&g_ccnt[e] = count;
            __threadfence();
            if (do_splits) {
                const int old = atomicAdd(&g_done, 1);
                if (old == NEV - 1) {
                    __threadfence();
                    int acc = 0;
                    out[splits_off] = 0.0f;
                    #pragma unroll
                    for (int ev = 0; ev < NEV; ++ev) {
                        acc += *(volatile int*)&g_ccnt[ev];
                        out[splits_off + 1 + ev] = (float)acc;
                    }
                }
            }
        }
    }
}

// ---------------------------------------------------------------------------
extern "C" void kernel_launch(void* const* d_in, const int* in_sizes, int n_in,
                              void* d_out, int out_size) {
    const float* x   = (const float*)d_in[0];
    float*       out = (float*)d_out;
    const long long n = (long long)out_size;

    // 1) fused zero(streaming) + pack + mailbox init
    zero_pack_kernel<<<NPTS / 256, 256>>>(x, out, n);

    // 2) condense + scatter + splits (128 blocks: single wave, poll-safe)
    const long long dout_elems = (long long)NPTS * NFEAT;
    const int do_splits = (n == dout_elems + NEV + 1) ? 1 : 0;
    condense_kernel<<<NEV * BPE, 1024>>>(x, out, dout_elems, do_splits);
}